// round 5
// baseline (speedup 1.0000x reference)
#include <cuda_runtime.h>
#include <math.h>

// Problem constants
#define HID   128
#define DI    2048
#define DT    768
#define KTOT  (DI + DT)        // 2816
#define NTASK 256
#define NQ    64

// Scratch: normalized support prototypes pn[256 tasks][4][128]
__device__ float g_pn[NTASK * 4 * HID];

__device__ __forceinline__ float warp_sum(float v) {
#pragma unroll
    for (int o = 16; o; o >>= 1) v += __shfl_xor_sync(0xffffffffu, v, o);
    return v;
}

// ---------------------------------------------------------------------------
// HID x HID GEMM from smem (cs, row stride 129) : out = cs @ W^T + bias
// 256 threads; each warp owns TPW tokens; each thread 4 dims (tx + 32j).
// Each warp touches only its own cs rows; ws is double-guarded by syncs.
// ---------------------------------------------------------------------------
template <int TPW>
__device__ __forceinline__ void gemm_hid(const float* cs, float* ws,
                                         const float* __restrict__ W,
                                         const float* __restrict__ bias,
                                         float (&acc)[TPW][4]) {
    const int tid = threadIdx.x;
    const int tx = tid & 31, ty = tid >> 5;
#pragma unroll
    for (int i = 0; i < TPW; i++)
#pragma unroll
        for (int j = 0; j < 4; j++) acc[i][j] = 0.f;

#pragma unroll
    for (int kt = 0; kt < 4; kt++) {
        __syncthreads();
#pragma unroll
        for (int i = 0; i < 16; i++) {  // 128*32 / 256
            int l = i * 256 + tid;
            int h = l >> 5, kk = l & 31;
            ws[kk * 129 + h] = W[h * HID + kt * 32 + kk];
        }
        __syncthreads();
#pragma unroll
        for (int kk = 0; kk < 32; kk++) {
            float xv[TPW];
#pragma unroll
            for (int i = 0; i < TPW; i++) xv[i] = cs[(ty * TPW + i) * 129 + kt * 32 + kk];
#pragma unroll
            for (int j = 0; j < 4; j++) {
                float w = ws[kk * 129 + tx + 32 * j];
#pragma unroll
                for (int i = 0; i < TPW; i++) acc[i][j] = fmaf(xv[i], w, acc[i][j]);
            }
        }
    }
#pragma unroll
    for (int j = 0; j < 4; j++) {
        float bb = bias[tx + 32 * j];
#pragma unroll
        for (int i = 0; i < TPW; i++) acc[i][j] += bb;
    }
}

// LayerNorm of register tile -> smem (row stride 129); warp-private rows.
template <int TPW>
__device__ __forceinline__ void ln_to_smem(float (&acc)[TPW][4],
                                           const float* __restrict__ g,
                                           const float* __restrict__ b,
                                           float* dst) {
    const int tid = threadIdx.x;
    const int tx = tid & 31, ty = tid >> 5;
#pragma unroll
    for (int i = 0; i < TPW; i++) {
        float s1 = 0.f, s2 = 0.f;
#pragma unroll
        for (int j = 0; j < 4; j++) { float x = acc[i][j]; s1 += x; s2 += x * x; }
        s1 = warp_sum(s1);
        s2 = warp_sum(s2);
        float m = s1 * (1.f / 128.f);
        float var = s2 * (1.f / 128.f) - m * m;
        float r = rsqrtf(var + 1e-5f);
        int tok = ty * TPW + i;
#pragma unroll
        for (int j = 0; j < 4; j++) {
            int h = tx + 32 * j;
            dst[tok * 129 + h] = (acc[i][j] - m) * r * g[h] + b[h];
        }
    }
}

// ---------------------------------------------------------------------------
// Support kernel: 128 blocks x 256 threads; 8 tokens (= 2 tasks) per block.
// Full attention path -> normalized prototypes g_pn.
// Static smem: 32*129 + 4*(8*129) + 32 = 8288 floats = 33.2 KB (< 48 KB).
// ---------------------------------------------------------------------------
#define SUP_SMEM (32 * 129 + 4 * (8 * 129) + 32)

__global__ __launch_bounds__(256) void support_kernel(
    const float* __restrict__ simg, const float* __restrict__ stxt,
    const float* __restrict__ Wi, const float* __restrict__ bi,
    const float* __restrict__ Wt, const float* __restrict__ bt,
    const float* __restrict__ g1, const float* __restrict__ b1,
    const float* __restrict__ Wq, const float* __restrict__ bq,
    const float* __restrict__ Wk, const float* __restrict__ bk,
    const float* __restrict__ Wv, const float* __restrict__ bv,
    const float* __restrict__ g2, const float* __restrict__ b2,
    const float* __restrict__ Wo, const float* __restrict__ bo) {
    __shared__ float sm[SUP_SMEM];
    float* ws = sm;                 // 32*129
    float* cs = ws + 32 * 129;      // 8*129
    float* qs = cs + 8 * 129;       // 8*129
    float* ks = qs + 8 * 129;       // 8*129
    float* vs = ks + 8 * 129;       // 8*129
    float* ss = vs + 8 * 129;       // 32 (2 tasks * 4x4 scores)
    float* xs = cs;                 // alias: 8*33=264 <= 8*129

    const int tid = threadIdx.x;
    const int tx = tid & 31, ty = tid >> 5;
    const int g0 = blockIdx.x * 8;  // first global support token

    // ---- phase 1: c = [img|txt] @ [Wi|Wt]^T ----
    float acc[1][4];
#pragma unroll
    for (int j = 0; j < 4; j++) acc[0][j] = 0.f;

    for (int kb = 0; kb < KTOT; kb += 32) {
        const float *xsrc, *wsrc;
        int xstr, wstr, koff;
        if (kb < DI) { xsrc = simg; xstr = DI; wsrc = Wi; wstr = DI; koff = kb; }
        else         { xsrc = stxt; xstr = DT; wsrc = Wt; wstr = DT; koff = kb - DI; }
        __syncthreads();
        {   // 8 tokens * 32 k = 256 elements, one per thread
            int tk = tid >> 5, kk = tid & 31;
            xs[tk * 33 + kk] = xsrc[(g0 + tk) * xstr + koff + kk];
        }
#pragma unroll
        for (int i = 0; i < 16; i++) {
            int l = i * 256 + tid;
            int h = l >> 5, kk = l & 31;
            ws[kk * 129 + h] = wsrc[h * wstr + koff + kk];
        }
        __syncthreads();
#pragma unroll
        for (int kk = 0; kk < 32; kk++) {
            float xv = xs[ty * 33 + kk];
#pragma unroll
            for (int j = 0; j < 4; j++)
                acc[0][j] = fmaf(xv, ws[kk * 129 + tx + 32 * j], acc[0][j]);
        }
    }
#pragma unroll
    for (int j = 0; j < 4; j++) {
        int h = tx + 32 * j;
        acc[0][j] += bi[h] + bt[h];
    }
    __syncthreads();  // xs (== cs region) dead everywhere before LN overwrites it

    // LN -> cs
    ln_to_smem<1>(acc, g1, b1, cs);

    // q, k, v projections
    gemm_hid<1>(cs, ws, Wq, bq, acc);
#pragma unroll
    for (int j = 0; j < 4; j++) qs[ty * 129 + tx + 32 * j] = acc[0][j];
    gemm_hid<1>(cs, ws, Wk, bk, acc);
#pragma unroll
    for (int j = 0; j < 4; j++) ks[ty * 129 + tx + 32 * j] = acc[0][j];
    gemm_hid<1>(cs, ws, Wv, bv, acc);
#pragma unroll
    for (int j = 0; j < 4; j++) vs[ty * 129 + tx + 32 * j] = acc[0][j];
    __syncthreads();

    // ---- attention scores: 2 tasks x 4x4 ----
    const float inv_scale = (float)(1.0 / (11.31370849898476 + 1e-8));  // 1/(sqrt(128)+1e-8)
    if (tid < 32) {
        int tl = tid >> 4, ii = (tid >> 2) & 3, jj = tid & 3;
        const float* qr = &qs[(tl * 4 + ii) * 129];
        const float* kr = &ks[(tl * 4 + jj) * 129];
        float s = 0.f;
#pragma unroll 8
        for (int h = 0; h < HID; h++) s = fmaf(qr[h], kr[h], s);
        ss[tid] = s * inv_scale;
    }
    __syncthreads();
    // softmax + (+1e-10, renorm, clip) per row  (8 rows)
    if (tid < 8) {
        float a0 = ss[tid * 4 + 0], a1 = ss[tid * 4 + 1];
        float a2 = ss[tid * 4 + 2], a3 = ss[tid * 4 + 3];
        float m = fmaxf(fmaxf(a0, a1), fmaxf(a2, a3));
        a0 = expf(a0 - m); a1 = expf(a1 - m); a2 = expf(a2 - m); a3 = expf(a3 - m);
        float s = a0 + a1 + a2 + a3;
        a0 /= s; a1 /= s; a2 /= s; a3 /= s;
        a0 += 1e-10f; a1 += 1e-10f; a2 += 1e-10f; a3 += 1e-10f;
        float s2 = a0 + a1 + a2 + a3;
        a0 /= s2; a1 /= s2; a2 /= s2; a3 /= s2;
        a0 = fminf(fmaxf(a0, 1e-7f), 1.f);
        a1 = fminf(fmaxf(a1, 1e-7f), 1.f);
        a2 = fminf(fmaxf(a2, 1e-7f), 1.f);
        a3 = fminf(fmaxf(a3, 1e-7f), 1.f);
        ss[tid * 4 + 0] = a0; ss[tid * 4 + 1] = a1;
        ss[tid * 4 + 2] = a2; ss[tid * 4 + 3] = a3;
    }
    __syncthreads();
    // ctx = a @ v  -> reuse qs
    {
        int h = tid & 127, part = tid >> 7;
#pragma unroll
        for (int u = 0; u < 4; u++) {
            int tok = part * 4 + u;
            int tl = tok >> 2, ii = tok & 3;
            float cv = 0.f;
#pragma unroll
            for (int jj = 0; jj < 4; jj++)
                cv = fmaf(ss[(tl * 4 + ii) * 4 + jj], vs[(tl * 4 + jj) * 129 + h], cv);
            qs[tok * 129 + h] = cv;
        }
    }
    __syncthreads();
    // LN(ctx) -> cs
    float tmp[1][4];
#pragma unroll
    for (int j = 0; j < 4; j++) tmp[0][j] = qs[ty * 129 + tx + 32 * j];
    ln_to_smem<1>(tmp, g2, b2, cs);

    // out = LN(ctx) @ Wo^T + bo
    gemm_hid<1>(cs, ws, Wo, bo, acc);

    // normalize rows -> g_pn
    {
        float s2 = 0.f;
#pragma unroll
        for (int j = 0; j < 4; j++) s2 += acc[0][j] * acc[0][j];
        s2 = warp_sum(s2);
        float inv = 1.f / fmaxf(sqrtf(s2), 1e-8f);
#pragma unroll
        for (int j = 0; j < 4; j++)
            g_pn[(g0 + ty) * HID + tx + 32 * j] = acc[0][j] * inv;
    }
}

// ---------------------------------------------------------------------------
// Query kernel: 512 blocks x 256 threads; 32 tokens per block (half a task).
// Attention over seqlen 1 is identity -> skip Wq/Wk entirely.
// Fuses c -> LN -> v -> LN -> Wo -> normalize -> logits.
// Static smem: 32*129 + 32*129 + 4*129 = 8772 floats = 35.1 KB (< 48 KB).
// ---------------------------------------------------------------------------
#define QRY_SMEM (32 * 129 + 32 * 129 + 4 * 129)

__global__ __launch_bounds__(256) void query_kernel(
    const float* __restrict__ qimg, const float* __restrict__ qtxt,
    const float* __restrict__ Wi, const float* __restrict__ bi,
    const float* __restrict__ Wt, const float* __restrict__ bt,
    const float* __restrict__ g1, const float* __restrict__ b1,
    const float* __restrict__ Wv, const float* __restrict__ bv,
    const float* __restrict__ g2, const float* __restrict__ b2,
    const float* __restrict__ Wo, const float* __restrict__ bo,
    float* __restrict__ out) {
    __shared__ float sm[QRY_SMEM];
    float* cs = sm;                 // 32*129
    float* ws = cs + 32 * 129;      // 32*129
    float* ps = ws + 32 * 129;      // 4*129 prototypes (padded rows)
    float* xs = cs;                 // alias: 32*33=1056 <= 32*129

    const int tid = threadIdx.x;
    const int tx = tid & 31, ty = tid >> 5;
    const int t = blockIdx.x >> 1;       // task
    const int g0 = blockIdx.x * 32;      // first global query token

    // prototypes for this task (512 values -> padded 4x129 rows)
#pragma unroll
    for (int i = 0; i < 2; i++) {
        int l = i * 256 + tid;
        int r = l >> 7, h = l & 127;
        ps[r * 129 + h] = g_pn[t * 4 * HID + l];
    }

    // ---- phase 1: c projection ----
    float acc[4][4];
#pragma unroll
    for (int i = 0; i < 4; i++)
#pragma unroll
        for (int j = 0; j < 4; j++) acc[i][j] = 0.f;

    for (int kb = 0; kb < KTOT; kb += 32) {
        const float *xsrc, *wsrc;
        int xstr, wstr, koff;
        if (kb < DI) { xsrc = qimg; xstr = DI; wsrc = Wi; wstr = DI; koff = kb; }
        else         { xsrc = qtxt; xstr = DT; wsrc = Wt; wstr = DT; koff = kb - DI; }
        __syncthreads();
#pragma unroll
        for (int i = 0; i < 4; i++) {  // 32 tokens * 32 k / 256
            int l = i * 256 + tid;
            int tk = l >> 5, kk = l & 31;
            xs[tk * 33 + kk] = xsrc[(g0 + tk) * xstr + koff + kk];
        }
#pragma unroll
        for (int i = 0; i < 16; i++) {
            int l = i * 256 + tid;
            int h = l >> 5, kk = l & 31;
            ws[kk * 129 + h] = wsrc[h * wstr + koff + kk];
        }
        __syncthreads();
#pragma unroll
        for (int kk = 0; kk < 32; kk++) {
            float xv[4];
#pragma unroll
            for (int i = 0; i < 4; i++) xv[i] = xs[(ty * 4 + i) * 33 + kk];
#pragma unroll
            for (int j = 0; j < 4; j++) {
                float w = ws[kk * 129 + tx + 32 * j];
#pragma unroll
                for (int i = 0; i < 4; i++) acc[i][j] = fmaf(xv[i], w, acc[i][j]);
            }
        }
    }
#pragma unroll
    for (int j = 0; j < 4; j++) {
        int h = tx + 32 * j;
        float bb = bi[h] + bt[h];
#pragma unroll
        for (int i = 0; i < 4; i++) acc[i][j] += bb;
    }
    __syncthreads();  // xs (== cs region) dead everywhere before LN overwrites it

    // LN(c) -> cs
    ln_to_smem<4>(acc, g1, b1, cs);

    // v = LN(c) @ Wv^T + bv  (== ctx: seqlen-1 attention is identity)
    gemm_hid<4>(cs, ws, Wv, bv, acc);

    // LN(v) -> cs  (each warp only touches its own rows; gemm already synced)
    ln_to_smem<4>(acc, g2, b2, cs);

    // qf = LN(v) @ Wo^T + bo
    gemm_hid<4>(cs, ws, Wo, bo, acc);

    // normalize rows -> cs (qn)
#pragma unroll
    for (int i = 0; i < 4; i++) {
        float s2 = 0.f;
#pragma unroll
        for (int j = 0; j < 4; j++) s2 += acc[i][j] * acc[i][j];
        s2 = warp_sum(s2);
        float inv = 1.f / fmaxf(sqrtf(s2), 1e-8f);
        int tok = ty * 4 + i;
#pragma unroll
        for (int j = 0; j < 4; j++)
            cs[tok * 129 + tx + 32 * j] = acc[i][j] * inv;
    }
    __syncthreads();

    // logits[g0+tok, c] = 10 * dot(qn[tok], pn[t][c])
    if (tid < 128) {
        int tok = tid >> 2, c = tid & 3;
        const float* qr = &cs[tok * 129];
        const float* pr = &ps[c * 129];
        float d = 0.f;
#pragma unroll 8
        for (int h = 0; h < HID; h++) d = fmaf(qr[h], pr[h], d);
        out[(g0 + tok) * 4 + c] = 10.f * d;
    }
}

// ---------------------------------------------------------------------------
extern "C" void kernel_launch(void* const* d_in, const int* in_sizes, int n_in,
                              void* d_out, int out_size) {
    const float* simg = (const float*)d_in[0];
    const float* stxt = (const float*)d_in[1];
    // d_in[2] = support_labels (int64) — unused by the reference output
    const float* qimg = (const float*)d_in[3];
    const float* qtxt = (const float*)d_in[4];
    const float* Wi = (const float*)d_in[5];
    const float* bi = (const float*)d_in[6];
    const float* Wt = (const float*)d_in[7];
    const float* bt = (const float*)d_in[8];
    const float* g1 = (const float*)d_in[9];
    const float* b1 = (const float*)d_in[10];
    const float* Wq = (const float*)d_in[11];
    const float* bq = (const float*)d_in[12];
    const float* Wk = (const float*)d_in[13];
    const float* bk = (const float*)d_in[14];
    const float* Wv = (const float*)d_in[15];
    const float* bv = (const float*)d_in[16];
    const float* g2 = (const float*)d_in[17];
    const float* b2 = (const float*)d_in[18];
    const float* Wo = (const float*)d_in[19];
    const float* bo = (const float*)d_in[20];
    float* out = (float*)d_out;

    support_kernel<<<128, 256>>>(simg, stxt, Wi, bi, Wt, bt, g1, b1,
                                 Wq, bq, Wk, bk, Wv, bv, g2, b2, Wo, bo);
    query_kernel<<<512, 256>>>(qimg, qtxt, Wi, bi, Wt, bt, g1, b1,
                               Wv, bv, g2, b2, Wo, bo, out);
}

// round 7
// speedup vs baseline: 1.2739x; 1.2739x over previous
#include <cuda_runtime.h>
#include <math.h>

// Problem constants
#define HID   128
#define DI    2048
#define DT    768
#define NTASK 256
#define NQ    64

#define QBLOCKS 256          // 256 blocks x 64 query tokens
#define SBLOCKS 16           // 16 blocks x 64 support tokens
#define WS_STRIDE 132        // weight tile row stride (floats), 16B-aligned reads
#define WS_FLOATS (16 * WS_STRIDE)   // 2112
#define CS_FLOATS (64 * 128)         // 8192
#define XS_STRIDE 20                 // staged input row stride (floats)

typedef unsigned long long ull;

// Scratch (device globals; no allocs)
__device__ float g_pn[NTASK * 4 * HID];       // normalized prototypes
__device__ float g_qn[NTASK * NQ * HID];      // normalized query features

// ---------------- packed f32x2 helpers (sm_103a FFMA2 path) ----------------
__device__ __forceinline__ ull splat2(float x) {
    ull r; asm("mov.b64 %0, {%1, %1};" : "=l"(r) : "f"(x)); return r;
}
__device__ __forceinline__ ull fma2(ull a, ull b, ull c) {
    ull d; asm("fma.rn.f32x2 %0, %1, %2, %3;" : "=l"(d) : "l"(a), "l"(b), "l"(c));
    return d;
}
__device__ __forceinline__ float2 unpack2(ull v) {
    float2 f; asm("mov.b64 {%0, %1}, %2;" : "=f"(f.x), "=f"(f.y) : "l"(v)); return f;
}

__device__ __forceinline__ float warp_sum(float v) {
#pragma unroll
    for (int o = 16; o; o >>= 1) v += __shfl_xor_sync(0xffffffffu, v, o);
    return v;
}

// ---------------------------------------------------------------------------
// 16-k-step MAC: acc[i][p] (p=0: dims 4tx,4tx+1; p=1: dims 4tx+2,4tx+3)
// xrow0 = this warp's first token row (stride XSTR floats, float4-aligned)
// ws[kk*132 + h]: reads are float4 at h=4tx -> conflict-free.
// ---------------------------------------------------------------------------
template <int XSTR>
__device__ __forceinline__ void mac16(const float* xrow0, const float* ws,
                                      ull (&acc)[8][2], int tx) {
#pragma unroll
    for (int kq = 0; kq < 4; kq++) {
        float4 xv[8];
#pragma unroll
        for (int i = 0; i < 8; i++)
            xv[i] = *(const float4*)(xrow0 + i * XSTR + kq * 4);
#pragma unroll
        for (int m = 0; m < 4; m++) {
            const int kk = kq * 4 + m;
            ulonglong2 wv = *(const ulonglong2*)(ws + kk * WS_STRIDE + tx * 4);
#pragma unroll
            for (int i = 0; i < 8; i++) {
                const float* xf = (const float*)&xv[i];
                ull x2 = splat2(xf[m]);
                acc[i][0] = fma2(x2, wv.x, acc[i][0]);
                acc[i][1] = fma2(x2, wv.y, acc[i][1]);
            }
        }
    }
}

// Stage a 16(k) x 128(h) weight tile into ws (cross-warp; caller syncs).
__device__ __forceinline__ void load_wtile(float* ws, const float* __restrict__ W,
                                           int wstr, int koff, int tid) {
#pragma unroll
    for (int r = 0; r < 2; r++) {
        int l = r * 256 + tid;          // 512 float4 slots
        int h = l >> 2, kq = l & 3;
        float4 w = *(const float4*)&W[h * wstr + koff + kq * 4];
        ws[(kq * 4 + 0) * WS_STRIDE + h] = w.x;
        ws[(kq * 4 + 1) * WS_STRIDE + h] = w.y;
        ws[(kq * 4 + 2) * WS_STRIDE + h] = w.z;
        ws[(kq * 4 + 3) * WS_STRIDE + h] = w.w;
    }
}

// HID x HID GEMM: vals-in-cs (warp-private rows) @ W^T -> acc
__device__ __forceinline__ void gemm128(const float* cs, float* ws,
                                        const float* __restrict__ W,
                                        ull (&acc)[8][2], int tid, int tx, int ty) {
#pragma unroll
    for (int i = 0; i < 8; i++) { acc[i][0] = 0ull; acc[i][1] = 0ull; }
#pragma unroll
    for (int kt = 0; kt < 8; kt++) {
        __syncthreads();
        load_wtile(ws, W, HID, kt * 16, tid);
        __syncthreads();
        mac16<128>(cs + ty * 8 * 128 + kt * 16, ws, acc, tx);
    }
}

// acc + bias -> vals[8][4] (dims 4tx..4tx+3)
__device__ __forceinline__ void acc_to_vals(ull (&acc)[8][2], float (&vals)[8][4],
                                            float b0, float b1, float b2, float b3) {
#pragma unroll
    for (int i = 0; i < 8; i++) {
        float2 a = unpack2(acc[i][0]);
        float2 b = unpack2(acc[i][1]);
        vals[i][0] = a.x + b0; vals[i][1] = a.y + b1;
        vals[i][2] = b.x + b2; vals[i][3] = b.y + b3;
    }
}

// LayerNorm vals -> cs (warp-private rows). Block-wide sync first: protects the
// xs-alias region (phase 1) from being overwritten while other warps still read.
__device__ __forceinline__ void ln_store(float (&vals)[8][4],
                                         const float* __restrict__ g,
                                         const float* __restrict__ b,
                                         float* cs, int tx, int ty) {
    __syncthreads();
    float4 gv = *(const float4*)&g[tx * 4];
    float4 bv = *(const float4*)&b[tx * 4];
#pragma unroll
    for (int i = 0; i < 8; i++) {
        float s1 = vals[i][0] + vals[i][1] + vals[i][2] + vals[i][3];
        float s2 = vals[i][0] * vals[i][0] + vals[i][1] * vals[i][1]
                 + vals[i][2] * vals[i][2] + vals[i][3] * vals[i][3];
        s1 = warp_sum(s1);
        s2 = warp_sum(s2);
        float m = s1 * (1.f / 128.f);
        float var = s2 * (1.f / 128.f) - m * m;
        float r = rsqrtf(var + 1e-5f);
        float4 o;
        o.x = (vals[i][0] - m) * r * gv.x + bv.x;
        o.y = (vals[i][1] - m) * r * gv.y + bv.y;
        o.z = (vals[i][2] - m) * r * gv.z + bv.z;
        o.w = (vals[i][3] - m) * r * gv.w + bv.w;
        *(float4*)&cs[(ty * 8 + i) * 128 + tx * 4] = o;
    }
}

// ---------------------------------------------------------------------------
// Fused main kernel: 272 blocks x 256 threads.
//   bid <  256: query blocks (64 tokens) -> g_qn   (seqlen-1 attn == identity)
//   bid >= 256: support blocks (64 tokens = 16 tasks) -> g_pn (full attention)
// smem: ws 2112 + cs 8192 = 10304 floats = 41.2 KB static (< 48 KB).
// ---------------------------------------------------------------------------
__global__ __launch_bounds__(256, 2) void main_kernel(
    const float* __restrict__ simg, const float* __restrict__ stxt,
    const float* __restrict__ qimg, const float* __restrict__ qtxt,
    const float* __restrict__ Wi, const float* __restrict__ bi,
    const float* __restrict__ Wt, const float* __restrict__ bt,
    const float* __restrict__ g1, const float* __restrict__ b1,
    const float* __restrict__ Wq, const float* __restrict__ bq,
    const float* __restrict__ Wk, const float* __restrict__ bk,
    const float* __restrict__ Wv, const float* __restrict__ bv,
    const float* __restrict__ g2, const float* __restrict__ b2,
    const float* __restrict__ Wo, const float* __restrict__ bo) {
    __shared__ float sm[WS_FLOATS + CS_FLOATS];
    float* ws = sm;
    float* cs = sm + WS_FLOATS;
    float* xs = cs;                 // alias: 64*20 = 1280 <= 8192

    const int tid = threadIdx.x;
    const int tx = tid & 31, ty = tid >> 5;
    const bool is_q = (blockIdx.x < QBLOCKS);
    const float* xi = is_q ? qimg : simg;
    const float* xt = is_q ? qtxt : stxt;
    const int g0 = (is_q ? blockIdx.x : (blockIdx.x - QBLOCKS)) * 64;

    ull acc[8][2];
#pragma unroll
    for (int i = 0; i < 8; i++) { acc[i][0] = 0ull; acc[i][1] = 0ull; }

    // ---- phase 1: c = [img|txt] @ [Wi|Wt]^T ----
    const int stage_tok = tid >> 2, stage_kq = tid & 3;
    for (int kt = 0; kt < 176; kt++) {
        const float* xsrc; const float* wsrc; int xstr, koff;
        if (kt < 128) { xsrc = xi; wsrc = Wi; xstr = DI; koff = kt * 16; }
        else          { xsrc = xt; wsrc = Wt; xstr = DT; koff = (kt - 128) * 16; }
        __syncthreads();
        *(float4*)&xs[stage_tok * XS_STRIDE + stage_kq * 4] =
            *(const float4*)&xsrc[(g0 + stage_tok) * xstr + koff + stage_kq * 4];
        load_wtile(ws, wsrc, xstr, koff, tid);
        __syncthreads();
        mac16<XS_STRIDE>(xs + ty * 8 * XS_STRIDE, ws, acc, tx);
    }

    float vals[8][4];
    {
        float4 ba = *(const float4*)&bi[tx * 4];
        float4 bb = *(const float4*)&bt[tx * 4];
        acc_to_vals(acc, vals, ba.x + bb.x, ba.y + bb.y, ba.z + bb.z, ba.w + bb.w);
    }

    // LN(c) -> cs
    ln_store(vals, g1, b1, cs, tx, ty);

    if (is_q) {
        // --- query path: attn(seqlen 1) == identity -> v is the context ---
        gemm128(cs, ws, Wv, acc, tid, tx, ty);
        {
            float4 b = *(const float4*)&bv[tx * 4];
            acc_to_vals(acc, vals, b.x, b.y, b.z, b.w);
        }
        ln_store(vals, g2, b2, cs, tx, ty);       // LN(v) -> cs
        gemm128(cs, ws, Wo, acc, tid, tx, ty);
        {
            float4 b = *(const float4*)&bo[tx * 4];
            acc_to_vals(acc, vals, b.x, b.y, b.z, b.w);
        }
        // normalize rows -> g_qn
#pragma unroll
        for (int i = 0; i < 8; i++) {
            float s2 = vals[i][0] * vals[i][0] + vals[i][1] * vals[i][1]
                     + vals[i][2] * vals[i][2] + vals[i][3] * vals[i][3];
            s2 = warp_sum(s2);
            float inv = 1.f / fmaxf(sqrtf(s2), 1e-8f);
            float4 o = { vals[i][0] * inv, vals[i][1] * inv,
                         vals[i][2] * inv, vals[i][3] * inv };
            *(float4*)&g_qn[(g0 + ty * 8 + i) * 128 + tx * 4] = o;
        }
    } else {
        // --- support path: full 4-token attention, all in registers/shuffles ---
        float q[8][4], k[8][4], s[8][4];

        gemm128(cs, ws, Wq, acc, tid, tx, ty);
        {
            float4 b = *(const float4*)&bq[tx * 4];
            acc_to_vals(acc, q, b.x, b.y, b.z, b.w);
        }
        gemm128(cs, ws, Wk, acc, tid, tx, ty);
        {
            float4 b = *(const float4*)&bk[tx * 4];
            acc_to_vals(acc, k, b.x, b.y, b.z, b.w);
        }

        // scores within each warp's 2 tasks (tokens i: group g = i>>2)
        const float inv_scale = (float)(1.0 / (11.31370849898476 + 1e-8));
#pragma unroll
        for (int i = 0; i < 8; i++) {
            int gbase = (i >> 2) * 4;
#pragma unroll
            for (int j = 0; j < 4; j++) {
                float p = q[i][0] * k[gbase + j][0] + q[i][1] * k[gbase + j][1]
                        + q[i][2] * k[gbase + j][2] + q[i][3] * k[gbase + j][3];
                s[i][j] = warp_sum(p) * inv_scale;
            }
        }
        // softmax + (+1e-10, renorm, clip) per row (redundant across lanes)
#pragma unroll
        for (int i = 0; i < 8; i++) {
            float a0 = s[i][0], a1 = s[i][1], a2 = s[i][2], a3 = s[i][3];
            float mx = fmaxf(fmaxf(a0, a1), fmaxf(a2, a3));
            a0 = expf(a0 - mx); a1 = expf(a1 - mx);
            a2 = expf(a2 - mx); a3 = expf(a3 - mx);
            float ssum = a0 + a1 + a2 + a3;
            a0 /= ssum; a1 /= ssum; a2 /= ssum; a3 /= ssum;
            a0 += 1e-10f; a1 += 1e-10f; a2 += 1e-10f; a3 += 1e-10f;
            float s2n = a0 + a1 + a2 + a3;
            a0 /= s2n; a1 /= s2n; a2 /= s2n; a3 /= s2n;
            s[i][0] = fminf(fmaxf(a0, 1e-7f), 1.f);
            s[i][1] = fminf(fmaxf(a1, 1e-7f), 1.f);
            s[i][2] = fminf(fmaxf(a2, 1e-7f), 1.f);
            s[i][3] = fminf(fmaxf(a3, 1e-7f), 1.f);
        }

        // v projection; ctx = a @ v (thread holds its 4 dims for all 8 tokens)
        gemm128(cs, ws, Wv, acc, tid, tx, ty);
        {
            float4 b = *(const float4*)&bv[tx * 4];
            acc_to_vals(acc, k, b.x, b.y, b.z, b.w);  // reuse k[] as v[]
        }
#pragma unroll
        for (int i = 0; i < 8; i++) {
            int gbase = (i >> 2) * 4;
#pragma unroll
            for (int m = 0; m < 4; m++) {
                vals[i][m] = s[i][0] * k[gbase + 0][m] + s[i][1] * k[gbase + 1][m]
                           + s[i][2] * k[gbase + 2][m] + s[i][3] * k[gbase + 3][m];
            }
        }

        // LN(ctx) -> cs; out = @ Wo^T + bo; normalize -> g_pn
        ln_store(vals, g2, b2, cs, tx, ty);
        gemm128(cs, ws, Wo, acc, tid, tx, ty);
        {
            float4 b = *(const float4*)&bo[tx * 4];
            acc_to_vals(acc, vals, b.x, b.y, b.z, b.w);
        }
#pragma unroll
        for (int i = 0; i < 8; i++) {
            float s2 = vals[i][0] * vals[i][0] + vals[i][1] * vals[i][1]
                     + vals[i][2] * vals[i][2] + vals[i][3] * vals[i][3];
            s2 = warp_sum(s2);
            float inv = 1.f / fmaxf(sqrtf(s2), 1e-8f);
            float4 o = { vals[i][0] * inv, vals[i][1] * inv,
                         vals[i][2] * inv, vals[i][3] * inv };
            *(float4*)&g_pn[(g0 + ty * 8 + i) * 128 + tx * 4] = o;
        }
    }
}

// ---------------------------------------------------------------------------
// Logits kernel: 256 blocks (one task) x 256 threads.
// logits[t, tok, c] = 10 * dot(qn[t,tok], pn[t,c])
// ---------------------------------------------------------------------------
__global__ __launch_bounds__(256) void logits_kernel(float* __restrict__ out) {
    __shared__ float pn[4 * 132];
    const int tid = threadIdx.x;
    const int t = blockIdx.x;
#pragma unroll
    for (int r = 0; r < 2; r++) {
        int l = r * 256 + tid;
        pn[(l >> 7) * 132 + (l & 127)] = g_pn[t * 512 + l];
    }
    __syncthreads();

    int tok = tid >> 2, c = tid & 3;
    const float* qr = &g_qn[(t * NQ + tok) * 128];
    const float* pr = &pn[c * 132];
    float d = 0.f;
#pragma unroll
    for (int u = 0; u < 32; u++) {
        float4 a = *(const float4*)&qr[u * 4];
        float4 b = *(const float4*)&pr[u * 4];
        d = fmaf(a.x, b.x, d); d = fmaf(a.y, b.y, d);
        d = fmaf(a.z, b.z, d); d = fmaf(a.w, b.w, d);
    }
    out[(t * NQ + tok) * 4 + c] = 10.f * d;
}

// ---------------------------------------------------------------------------
extern "C" void kernel_launch(void* const* d_in, const int* in_sizes, int n_in,
                              void* d_out, int out_size) {
    const float* simg = (const float*)d_in[0];
    const float* stxt = (const float*)d_in[1];
    // d_in[2] = support_labels (int64) — unused by the reference output
    const float* qimg = (const float*)d_in[3];
    const float* qtxt = (const float*)d_in[4];
    const float* Wi = (const float*)d_in[5];
    const float* bi = (const float*)d_in[6];
    const float* Wt = (const float*)d_in[7];
    const float* bt = (const float*)d_in[8];
    const float* g1 = (const float*)d_in[9];
    const float* b1 = (const float*)d_in[10];
    const float* Wq = (const float*)d_in[11];
    const float* bq = (const float*)d_in[12];
    const float* Wk = (const float*)d_in[13];
    const float* bk = (const float*)d_in[14];
    const float* Wv = (const float*)d_in[15];
    const float* bv = (const float*)d_in[16];
    const float* g2 = (const float*)d_in[17];
    const float* b2 = (const float*)d_in[18];
    const float* Wo = (const float*)d_in[19];
    const float* bo = (const float*)d_in[20];
    float* out = (float*)d_out;

    main_kernel<<<QBLOCKS + SBLOCKS, 256>>>(simg, stxt, qimg, qtxt,
                                            Wi, bi, Wt, bt, g1, b1,
                                            Wq, bq, Wk, bk, Wv, bv,
                                            g2, b2, Wo, bo);
    logits_kernel<<<NTASK, 256>>>(out);
}